// round 4
// baseline (speedup 1.0000x reference)
#include <cuda_runtime.h>
#include <cstdint>

#define N_NODES 50000
#define N_EDGES 600000
#define DIM 128

// ---------------------------------------------------------------------------
// Scratch (no device allocation allowed -> __device__ globals)
// ---------------------------------------------------------------------------
__device__ float        g_edge[N_EDGES];    // logits, then overwritten with exp()
__device__ unsigned int g_segmax[N_NODES];  // monotone-encoded float max per dst
__device__ float        g_segsum[N_NODES];  // sum of exp per dst

// Monotone float <-> uint mapping: f1 < f2  <=>  enc(f1) < enc(f2) (as unsigned).
// All encoded finite values are > 0, so zero-init acts as -inf.
__device__ __forceinline__ unsigned enc_f(float f) {
    unsigned u = __float_as_uint(f);
    return (u & 0x80000000u) ? ~u : (u | 0x80000000u);
}
__device__ __forceinline__ float dec_f(unsigned u) {
    return __uint_as_float((u & 0x80000000u) ? (u & 0x7fffffffu) : ~u);
}

// ---------------------------------------------------------------------------
// K0: zero out + scratch
// ---------------------------------------------------------------------------
__global__ void k_init(float4* __restrict__ out4) {
    int i = blockIdx.x * blockDim.x + threadIdx.x;
    if (i < N_NODES) {
        g_segmax[i] = 0u;
        g_segsum[i] = 0.0f;
    }
    if (i < N_NODES * (DIM / 4)) {
        out4[i] = make_float4(0.f, 0.f, 0.f, 0.f);
    }
}

// ---------------------------------------------------------------------------
// K1: per-edge logits (one warp per edge) + segment max
//   logit = dot(ft_s*ft_d*h_d, W_pi) * sigmoid(dot(ft_s*ft_d, W_M[:128]) +
//                                               dot(h_d,       W_M[128:]))
// ---------------------------------------------------------------------------
__global__ void __launch_bounds__(256)
k_logits(const float* __restrict__ h_v, const float* __restrict__ h_d,
         const float* __restrict__ W_pi, const float* __restrict__ W_M,
         const int* __restrict__ src, const int* __restrict__ dst) {
    int e    = (blockIdx.x * blockDim.x + threadIdx.x) >> 5;
    int lane = threadIdx.x & 31;
    if (e >= N_EDGES) return;

    int s = src[e];   // broadcast LDG within warp
    int d = dst[e];

    const float4* vs = reinterpret_cast<const float4*>(h_v + (size_t)s * DIM);
    const float4* vd = reinterpret_cast<const float4*>(h_v + (size_t)d * DIM);
    const float4* hd = reinterpret_cast<const float4*>(h_d + (size_t)e * DIM);

    float4 a = vs[lane];
    float4 b = vd[lane];
    float4 c = hd[lane];
    float4 p = make_float4(a.x * b.x, a.y * b.y, a.z * b.z, a.w * b.w);

    float4 wp  = reinterpret_cast<const float4*>(W_pi)[lane];
    float4 wm1 = reinterpret_cast<const float4*>(W_M)[lane];
    float4 wm2 = reinterpret_cast<const float4*>(W_M)[lane + 32];

    float ev = p.x * c.x * wp.x + p.y * c.y * wp.y
             + p.z * c.z * wp.z + p.w * c.w * wp.w;
    float mv = p.x * wm1.x + p.y * wm1.y + p.z * wm1.z + p.w * wm1.w
             + c.x * wm2.x + c.y * wm2.y + c.z * wm2.z + c.w * wm2.w;

    #pragma unroll
    for (int o = 16; o; o >>= 1) {
        ev += __shfl_xor_sync(0xffffffff, ev, o);
        mv += __shfl_xor_sync(0xffffffff, mv, o);
    }

    if (lane == 0) {
        float sig   = 1.0f / (1.0f + expf(-mv));
        float logit = ev * sig;
        g_edge[e] = logit;
        atomicMax(&g_segmax[d], enc_f(logit));
    }
}

// ---------------------------------------------------------------------------
// K2: per-edge exp(logit - max) + segment sum (one thread per edge)
// ---------------------------------------------------------------------------
__global__ void __launch_bounds__(256)
k_exp(const int* __restrict__ dst) {
    int e = blockIdx.x * blockDim.x + threadIdx.x;
    if (e >= N_EDGES) return;
    int d = dst[e];
    float m  = dec_f(g_segmax[d]);
    float ex = expf(g_edge[e] - m);
    g_edge[e] = ex;
    atomicAdd(&g_segsum[d], ex);
}

// ---------------------------------------------------------------------------
// K3: per-edge aggregation (one warp per edge)
//   out[dst] += h_v[src] * (ex / segsum[dst])   via red.global.add.v4.f32
// ---------------------------------------------------------------------------
__global__ void __launch_bounds__(256)
k_agg(const float* __restrict__ h_v,
      const int* __restrict__ src, const int* __restrict__ dst,
      float* __restrict__ out) {
    int e    = (blockIdx.x * blockDim.x + threadIdx.x) >> 5;
    int lane = threadIdx.x & 31;
    if (e >= N_EDGES) return;

    int s = src[e];
    int d = dst[e];
    float a = g_edge[e] / g_segsum[d];

    float4 v = reinterpret_cast<const float4*>(h_v + (size_t)s * DIM)[lane];
    float4 m = make_float4(v.x * a, v.y * a, v.z * a, v.w * a);

    float* addr = out + (size_t)d * DIM + lane * 4;
    asm volatile("red.global.add.v4.f32 [%0], {%1, %2, %3, %4};"
                 :: "l"(addr), "f"(m.x), "f"(m.y), "f"(m.z), "f"(m.w)
                 : "memory");
}

// ---------------------------------------------------------------------------
// Launch
// Inputs (metadata order): h_v[50000*128] f32, h_d[600000*128] f32,
//   W_pi[128] f32, W_M[256] f32, src[600000] i32, dst[600000] i32
// Output: [50000*128] f32
// ---------------------------------------------------------------------------
extern "C" void kernel_launch(void* const* d_in, const int* in_sizes, int n_in,
                              void* d_out, int out_size) {
    const float* h_v  = (const float*)d_in[0];
    const float* h_d  = (const float*)d_in[1];
    const float* W_pi = (const float*)d_in[2];
    const float* W_M  = (const float*)d_in[3];
    const int*   src  = (const int*)d_in[4];
    const int*   dst  = (const int*)d_in[5];
    float*       out  = (float*)d_out;

    // K0: zero out + scratch. Covers max(N_NODES, N_NODES*DIM/4) threads.
    {
        int n = N_NODES * (DIM / 4);       // 1.6M
        int blocks = (n + 255) / 256;
        k_init<<<blocks, 256>>>(reinterpret_cast<float4*>(out));
    }

    // K1: logits + segment max (1 warp / edge)
    {
        long long threads = (long long)N_EDGES * 32;
        int blocks = (int)((threads + 255) / 256);
        k_logits<<<blocks, 256>>>(h_v, h_d, W_pi, W_M, src, dst);
    }

    // K2: exp + segment sum (1 thread / edge)
    {
        int blocks = (N_EDGES + 255) / 256;
        k_exp<<<blocks, 256>>>(dst);
    }

    // K3: weighted aggregation (1 warp / edge)
    {
        long long threads = (long long)N_EDGES * 32;
        int blocks = (int)((threads + 255) / 256);
        k_agg<<<blocks, 256>>>(h_v, src, dst, out);
    }
}

// round 8
// speedup vs baseline: 1.0751x; 1.0751x over previous
#include <cuda_runtime.h>
#include <cstdint>
#include <cfloat>

#define N_NODES 50000
#define N_EDGES 600000
#define DIM 128

// ---------------------------------------------------------------------------
// Scratch (__device__ globals; no allocation allowed)
// ---------------------------------------------------------------------------
__device__ unsigned g_hist[N_NODES];     // in-degree histogram
__device__ unsigned g_cnt[N_NODES];      // scatter cursors
__device__ int      g_row[N_NODES + 1];  // CSR row pointers (by dst)
__device__ int      g_pos[N_EDGES];      // original edge -> sorted slot
__device__ int      g_srcs[N_EDGES];     // src id in sorted order
__device__ float    g_logit[N_EDGES];    // logits in sorted order

// ---------------------------------------------------------------------------
// K0: zero histogram + cursors
// ---------------------------------------------------------------------------
__global__ void k_init() {
    int i = blockIdx.x * blockDim.x + threadIdx.x;
    if (i < N_NODES) {
        g_hist[i] = 0u;
        g_cnt[i]  = 0u;
    }
}

// ---------------------------------------------------------------------------
// K1: in-degree histogram
// ---------------------------------------------------------------------------
__global__ void __launch_bounds__(256)
k_hist(const int* __restrict__ dst) {
    int e = blockIdx.x * blockDim.x + threadIdx.x;
    if (e < N_EDGES) atomicAdd(&g_hist[dst[e]], 1u);
}

// ---------------------------------------------------------------------------
// K2: exclusive scan of histogram -> row pointers (single block, 1024 thr)
// ---------------------------------------------------------------------------
__global__ void __launch_bounds__(1024)
k_scan() {
    __shared__ int sh[1024];
    const int TPT = (N_NODES + 1023) / 1024;  // 49
    int t    = threadIdx.x;
    int base = t * TPT;

    // local sum of this thread's chunk
    int local = 0;
    for (int i = 0; i < TPT; ++i) {
        int idx = base + i;
        if (idx < N_NODES) local += (int)g_hist[idx];
    }
    sh[t] = local;
    __syncthreads();

    // Hillis-Steele inclusive scan over 1024 partials
    for (int d = 1; d < 1024; d <<= 1) {
        int v = (t >= d) ? sh[t - d] : 0;
        __syncthreads();
        sh[t] += v;
        __syncthreads();
    }
    int off = (t == 0) ? 0 : sh[t - 1];  // exclusive prefix for this chunk

    // second pass: write exclusive prefix per node
    int run = off;
    for (int i = 0; i < TPT; ++i) {
        int idx = base + i;
        if (idx < N_NODES) {
            g_row[idx] = run;
            run += (int)g_hist[idx];
        }
    }
    if (t == 0) g_row[N_NODES] = N_EDGES;
}

// ---------------------------------------------------------------------------
// K3: scatter edges into dst-sorted order
// ---------------------------------------------------------------------------
__global__ void __launch_bounds__(256)
k_scatter(const int* __restrict__ src, const int* __restrict__ dst) {
    int e = blockIdx.x * blockDim.x + threadIdx.x;
    if (e >= N_EDGES) return;
    int d = dst[e];
    int p = g_row[d] + (int)atomicAdd(&g_cnt[d], 1u);
    g_pos[e]  = p;
    g_srcs[p] = src[e];
}

// ---------------------------------------------------------------------------
// K4: per-edge logits (warp handles EPW consecutive edges, weights hoisted)
//   logit = dot(fs*fd*hd, W_pi) * sigmoid(dot(fs*fd, W_M[:128]) +
//                                         dot(hd,    W_M[128:]))
//   written into the dst-sorted slot g_pos[e].
// ---------------------------------------------------------------------------
#define EPW 4
__global__ void __launch_bounds__(256)
k_logits(const float* __restrict__ h_v, const float* __restrict__ h_d,
         const float* __restrict__ W_pi, const float* __restrict__ W_M,
         const int* __restrict__ src, const int* __restrict__ dst) {
    int warp = (blockIdx.x * blockDim.x + threadIdx.x) >> 5;
    int lane = threadIdx.x & 31;
    int e0   = warp * EPW;
    if (e0 >= N_EDGES) return;

    // hoist weight vectors (identical across all edges)
    float4 wp  = reinterpret_cast<const float4*>(W_pi)[lane];
    float4 wm1 = reinterpret_cast<const float4*>(W_M)[lane];
    float4 wm2 = reinterpret_cast<const float4*>(W_M)[lane + 32];

    const float4* hv4 = reinterpret_cast<const float4*>(h_v);
    const float4* hd4 = reinterpret_cast<const float4*>(h_d);

    #pragma unroll
    for (int it = 0; it < EPW; ++it) {
        int e = e0 + it;
        if (e >= N_EDGES) break;

        int s = src[e];   // lane-uniform broadcast loads
        int d = dst[e];

        float4 a = hv4[(size_t)s * 32 + lane];
        float4 b = hv4[(size_t)d * 32 + lane];
        float4 c = hd4[(size_t)e * 32 + lane];
        float4 p = make_float4(a.x * b.x, a.y * b.y, a.z * b.z, a.w * b.w);

        float ev = p.x * c.x * wp.x + p.y * c.y * wp.y
                 + p.z * c.z * wp.z + p.w * c.w * wp.w;
        float mv = p.x * wm1.x + p.y * wm1.y + p.z * wm1.z + p.w * wm1.w
                 + c.x * wm2.x + c.y * wm2.y + c.z * wm2.z + c.w * wm2.w;

        #pragma unroll
        for (int o = 16; o; o >>= 1) {
            ev += __shfl_xor_sync(0xffffffff, ev, o);
            mv += __shfl_xor_sync(0xffffffff, mv, o);
        }

        if (lane == 0) {
            float sig = 1.0f / (1.0f + expf(-mv));
            g_logit[g_pos[e]] = ev * sig;
        }
    }
}

// ---------------------------------------------------------------------------
// K5: per-node softmax + weighted aggregation (one warp per node, no atomics)
//   out[n] = (sum_e exp(l_e - max) * h_v[src_e]) / (sum_e exp(l_e - max))
// ---------------------------------------------------------------------------
__global__ void __launch_bounds__(256)
k_node(const float* __restrict__ h_v, float* __restrict__ out) {
    int n    = (blockIdx.x * blockDim.x + threadIdx.x) >> 5;
    int lane = threadIdx.x & 31;
    if (n >= N_NODES) return;

    int beg = g_row[n];
    int end = g_row[n + 1];

    float4* out4 = reinterpret_cast<float4*>(out) + (size_t)n * 32 + lane;

    if (end == beg) {                       // no incoming edges -> zeros
        *out4 = make_float4(0.f, 0.f, 0.f, 0.f);
        return;
    }

    // strided segment max
    float mx = -FLT_MAX;
    for (int j = beg + lane; j < end; j += 32)
        mx = fmaxf(mx, g_logit[j]);
    #pragma unroll
    for (int o = 16; o; o >>= 1)
        mx = fmaxf(mx, __shfl_xor_sync(0xffffffff, mx, o));

    // serial accumulate: each lane owns a float4 slice of DIM
    const float4* hv4 = reinterpret_cast<const float4*>(h_v);
    float4 acc = make_float4(0.f, 0.f, 0.f, 0.f);
    float  sum = 0.f;
    for (int j = beg; j < end; ++j) {
        float l  = g_logit[j];              // lane-uniform broadcast
        int   s  = g_srcs[j];               // lane-uniform broadcast
        float ex = expf(l - mx);
        sum += ex;
        float4 v = hv4[(size_t)s * 32 + lane];
        acc.x = fmaf(v.x, ex, acc.x);
        acc.y = fmaf(v.y, ex, acc.y);
        acc.z = fmaf(v.z, ex, acc.z);
        acc.w = fmaf(v.w, ex, acc.w);
    }

    float inv = 1.0f / sum;
    *out4 = make_float4(acc.x * inv, acc.y * inv, acc.z * inv, acc.w * inv);
}

// ---------------------------------------------------------------------------
// Launch
// Inputs (metadata order): h_v[50000*128] f32, h_d[600000*128] f32,
//   W_pi[128] f32, W_M[256] f32, src[600000] i32, dst[600000] i32
// Output: [50000*128] f32
// ---------------------------------------------------------------------------
extern "C" void kernel_launch(void* const* d_in, const int* in_sizes, int n_in,
                              void* d_out, int out_size) {
    const float* h_v  = (const float*)d_in[0];
    const float* h_d  = (const float*)d_in[1];
    const float* W_pi = (const float*)d_in[2];
    const float* W_M  = (const float*)d_in[3];
    const int*   src  = (const int*)d_in[4];
    const int*   dst  = (const int*)d_in[5];
    float*       out  = (float*)d_out;

    k_init<<<(N_NODES + 255) / 256, 256>>>();
    k_hist<<<(N_EDGES + 255) / 256, 256>>>(dst);
    k_scan<<<1, 1024>>>();
    k_scatter<<<(N_EDGES + 255) / 256, 256>>>(src, dst);

    {   // K4: logits — one warp per EPW edges
        long long warps  = (N_EDGES + EPW - 1) / EPW;
        int blocks = (int)((warps * 32 + 255) / 256);
        k_logits<<<blocks, 256>>>(h_v, h_d, W_pi, W_M, src, dst);
    }
    {   // K5: per-node softmax + aggregation — one warp per node
        long long warps  = N_NODES;
        int blocks = (int)((warps * 32 + 255) / 256);
        k_node<<<blocks, 256>>>(h_v, out);
    }
}